// round 9
// baseline (speedup 1.0000x reference)
#include <cuda_runtime.h>
#include <cstdint>
#include <cstddef>

#define NSCORE       256
#define DIM          64
#define N_ITEMS_TOT  500000
#define TILE_N       64
#define NTILES       ((N_ITEMS_TOT + TILE_N - 1) / TILE_N)   // 7813
#define ROWPAD       68                                       // 64 + 4 floats pad

// ---------------- baseline-PTX helpers (sm_80+, OK on .target sm_103) ----------------
static __device__ __forceinline__ uint32_t f2tf32(float x) {
    uint32_t r;
    asm("cvt.rna.tf32.f32 %0, %1;" : "=r"(r) : "f"(x));
    return r;
}
static __device__ __forceinline__ void mma_tf32(float d[4], const uint32_t a[4],
                                                const uint32_t b0, const uint32_t b1) {
    asm volatile("mma.sync.aligned.m16n8k8.row.col.f32.tf32.tf32.f32 "
                 "{%0,%1,%2,%3}, {%4,%5,%6,%7}, {%8,%9}, {%0,%1,%2,%3};"
                 : "+f"(d[0]), "+f"(d[1]), "+f"(d[2]), "+f"(d[3])
                 : "r"(a[0]), "r"(a[1]), "r"(a[2]), "r"(a[3]), "r"(b0), "r"(b1));
}
static __device__ __forceinline__ uint32_t smem_u32(const void* p) {
    uint32_t a;
    asm("{ .reg .u64 t; cvta.to.shared.u64 t, %1; cvt.u32.u64 %0, t; }" : "=r"(a) : "l"(p));
    return a;
}
#define CP_COMMIT()   asm volatile("cp.async.commit_group;" ::: "memory")
#define CP_WAIT1()    asm volatile("cp.async.wait_group 1;" ::: "memory")

// ---------------- persistent state: prologue -> main ----------------
__device__ __align__(16) float g_users[NSCORE * DIM];
__device__ float g_usq[NSCORE];

__global__ void cml_prep_users(const int* __restrict__ ids,
                               const float* __restrict__ U) {
    int m = threadIdx.x;                       // 256 threads, one user each
    const float* row = U + (size_t)ids[m] * DIM;
    float s = 0.f;
#pragma unroll 8
    for (int k = 0; k < DIM; k++) {
        float x = row[k];
        g_users[m * DIM + k] = x;
        s = fmaf(x, x, s);
    }
    g_usq[m] = s;
}

// cp.async one 64x64 fp32 item tile into a padded smem stage. Per-row guard:
// OOB rows are simply not loaded (epilogue column guard contains the garbage).
static __device__ __forceinline__ void cp_tile(const float* __restrict__ items,
                                               uint32_t dst_u32, int tile_base, int tid) {
    const char* src = reinterpret_cast<const char*>(items + (size_t)tile_base * DIM);
#pragma unroll
    for (int j = 0; j < 2; j++) {
        int idx = j * 512 + tid;               // 16B-chunk index (1024 per tile)
        int r = idx >> 4;                      // 16 chunks per item row
        int c = idx & 15;
        if (tile_base + r < N_ITEMS_TOT) {
            uint32_t d = dst_u32 + (uint32_t)(r * ROWPAD + c * 4) * 4u;
            asm volatile("cp.async.cg.shared.global [%0], [%1], 16;"
                         :: "r"(d), "l"(src + (size_t)idx * 16) : "memory");
        }
    }
}

// ||i||^2 for all 64 rows of a stage: 8 threads/row, fp32 exact, 3-shfl reduce.
static __device__ __forceinline__ void isq_tile(const float* __restrict__ st,
                                                float* __restrict__ isq, int tid) {
    int r = tid >> 3, q = tid & 7;
    const float4* p = reinterpret_cast<const float4*>(st + r * ROWPAD + q * 8);
    float4 a = p[0], b = p[1];
    float s = fmaf(a.x, a.x, fmaf(a.y, a.y, fmaf(a.z, a.z, a.w * a.w)));
    s = fmaf(b.x, b.x, fmaf(b.y, b.y, fmaf(b.z, b.z, fmaf(b.w, b.w, s))));
    s += __shfl_xor_sync(0xffffffffu, s, 4);
    s += __shfl_xor_sync(0xffffffffu, s, 2);
    s += __shfl_xor_sync(0xffffffffu, s, 1);
    if (q == 0) isq[r] = s;
}

__global__ void __launch_bounds__(512, 1)
cml_main(const float* __restrict__ items, float* __restrict__ out) {
    __shared__ float sm_it[2][TILE_N * ROWPAD];   // raw fp32 item tiles, 2 x 17408 B
    __shared__ float sm_isq[2][TILE_N];

    int tid = threadIdx.x, wid = tid >> 5, lane = tid & 31;
    int grp = lane >> 2, tig = lane & 3;
    int bx = blockIdx.x, G = gridDim.x;
    int cnt = (NTILES - bx + G - 1) / G;

    uint32_t s0 = smem_u32(sm_it[0]), s1 = smem_u32(sm_it[1]);

    // Prefetch tiles 0 and 1 immediately (row guard no-ops OOB tiles).
    cp_tile(items, s0, bx * TILE_N, tid);
    CP_COMMIT();
    cp_tile(items, s1, (bx + G) * TILE_N, tid);
    CP_COMMIT();

    // A fragments (16 users per warp, tf32) resident in registers; overlaps cp.async.
    // reg0:(r0, c) reg1:(r0+8, c) reg2:(r0, c+4) reg3:(r0+8, c+4)
    int r0 = wid * 16 + grp;
    uint32_t A[8][4];
#pragma unroll
    for (int ks = 0; ks < 8; ks++) {
        int c = ks * 8 + tig;
        A[ks][0] = f2tf32(g_users[r0 * DIM + c]);
        A[ks][1] = f2tf32(g_users[(r0 + 8) * DIM + c]);
        A[ks][2] = f2tf32(g_users[r0 * DIM + c + 4]);
        A[ks][3] = f2tf32(g_users[(r0 + 8) * DIM + c + 4]);
    }
    float nu0 = -g_usq[r0], nu1 = -g_usq[r0 + 8];

    CP_WAIT1();                               // tile 0 landed
    __syncthreads();
    isq_tile(sm_it[0], sm_isq[0], tid);

    for (int i = 0; i < cnt; i++) {
        int cur = i & 1, nxt = cur ^ 1;
        int tile_base = (bx + i * G) * TILE_N;
        __syncthreads();                      // isq[cur] visible (+ stage cur data)

        // ---- MMA: cross[16 users x 64 items], tf32 cvt fused after LDS ----
        float C[8][4];
#pragma unroll
        for (int ni = 0; ni < 8; ni++)
#pragma unroll
            for (int q = 0; q < 4; q++) C[ni][q] = 0.f;

        const float* st = sm_it[cur];
#pragma unroll
        for (int ks = 0; ks < 8; ks++) {
            int koff = ks * 8 + tig;
#pragma unroll
            for (int ni = 0; ni < 8; ni++) {
                const float* bp = st + (ni * 8 + grp) * ROWPAD + koff;  // conflict-free
                uint32_t b0 = f2tf32(bp[0]);
                uint32_t b1 = f2tf32(bp[4]);
                mma_tf32(C[ni], A[ks], b0, b1);
            }
        }

        // ---- epilogue: score = 2*cross - usq - isq, streaming float2 stores ----
        const float* isq = sm_isq[cur];
        float* row0 = out + (size_t)r0 * N_ITEMS_TOT;
        float* row1 = out + (size_t)(r0 + 8) * N_ITEMS_TOT;
#pragma unroll
        for (int ni = 0; ni < 8; ni++) {
            int cl = ni * 8 + 2 * tig;
            int col = tile_base + cl;
            if (col < N_ITEMS_TOT) {
                float2 iq = *reinterpret_cast<const float2*>(isq + cl);
                float2 v0, v1;
                v0.x = fmaf(2.f, C[ni][0], nu0 - iq.x);
                v0.y = fmaf(2.f, C[ni][1], nu0 - iq.y);
                v1.x = fmaf(2.f, C[ni][2], nu1 - iq.x);
                v1.y = fmaf(2.f, C[ni][3], nu1 - iq.y);
                __stcs(reinterpret_cast<float2*>(row0 + col), v0);
                __stcs(reinterpret_cast<float2*>(row1 + col), v1);
            }
        }

        if (i + 1 < cnt) {
            __syncthreads();                  // all warps done reading stage cur
            uint32_t scur = cur ? s1 : s0;
            cp_tile(items, scur, (bx + (i + 2) * G) * TILE_N, tid);  // tile i+2
            CP_COMMIT();
            CP_WAIT1();                       // tile i+1 landed
            __syncthreads();                  // visible to all warps
            isq_tile(sm_it[nxt], sm_isq[nxt], tid);
        }
    }
}

extern "C" void kernel_launch(void* const* d_in, const int* in_sizes, int n_in,
                              void* d_out, int out_size) {
    (void)in_sizes; (void)n_in; (void)out_size;
    const int*   ids   = (const int*)d_in[0];
    const float* users = (const float*)d_in[1];
    const float* items = (const float*)d_in[2];
    float*       out   = (float*)d_out;

    int sms = 148;
    cudaDeviceGetAttribute(&sms, cudaDevAttrMultiProcessorCount, 0);
    int grid = sms < NTILES ? sms : NTILES;

    cml_prep_users<<<1, 256>>>(ids, users);
    cml_main<<<grid, 512>>>(items, out);
}

// round 10
// speedup vs baseline: 1.0239x; 1.0239x over previous
#include <cuda_runtime.h>
#include <cstdint>
#include <cstddef>

#define NSCORE       256
#define DIM          64
#define N_ITEMS_TOT  500000
#define TILE_N       64
#define NTILES       ((N_ITEMS_TOT + TILE_N - 1) / TILE_N)   // 7813
#define ROWPAD       68                                       // 64 + 4 floats pad

// ---------------- baseline-PTX helpers (sm_80+, OK on .target sm_103) ----------------
static __device__ __forceinline__ uint32_t f2tf32(float x) {
    uint32_t r;
    asm("cvt.rna.tf32.f32 %0, %1;" : "=r"(r) : "f"(x));
    return r;
}
static __device__ __forceinline__ void mma_tf32(float d[4], const uint32_t a[4],
                                                const uint32_t b0, const uint32_t b1) {
    asm volatile("mma.sync.aligned.m16n8k8.row.col.f32.tf32.tf32.f32 "
                 "{%0,%1,%2,%3}, {%4,%5,%6,%7}, {%8,%9}, {%0,%1,%2,%3};"
                 : "+f"(d[0]), "+f"(d[1]), "+f"(d[2]), "+f"(d[3])
                 : "r"(a[0]), "r"(a[1]), "r"(a[2]), "r"(a[3]), "r"(b0), "r"(b1));
}
static __device__ __forceinline__ uint32_t smem_u32(const void* p) {
    uint32_t a;
    asm("{ .reg .u64 t; cvta.to.shared.u64 t, %1; cvt.u32.u64 %0, t; }" : "=r"(a) : "l"(p));
    return a;
}
#define CP_COMMIT()   asm volatile("cp.async.commit_group;" ::: "memory")
#define CP_WAIT1()    asm volatile("cp.async.wait_group 1;" ::: "memory")

// ---------------- persistent state: prologue -> main ----------------
__device__ __align__(16) float g_users[NSCORE * DIM];
__device__ float g_usq[NSCORE];

__global__ void cml_prep_users(const int* __restrict__ ids,
                               const float* __restrict__ U) {
    int m = threadIdx.x;                       // 256 threads, one user each
    const float* row = U + (size_t)ids[m] * DIM;
    float s = 0.f;
#pragma unroll 8
    for (int k = 0; k < DIM; k++) {
        float x = row[k];
        g_users[m * DIM + k] = x;
        s = fmaf(x, x, s);
    }
    g_usq[m] = s;
}

// cp.async one 64x64 fp32 item tile into a padded smem stage (raw fp32).
// OOB rows simply not loaded; epilogue column guard contains garbage.
static __device__ __forceinline__ void cp_tile(const float* __restrict__ items,
                                               uint32_t dst_u32, int tile_base, int tid) {
    const char* src = reinterpret_cast<const char*>(items + (size_t)tile_base * DIM);
#pragma unroll
    for (int j = 0; j < 2; j++) {
        int idx = j * 512 + tid;               // 16B-chunk index (1024 per tile)
        int r = idx >> 4;                      // 16 chunks per item row
        int c = idx & 15;
        if (tile_base + r < N_ITEMS_TOT) {
            uint32_t d = dst_u32 + (uint32_t)(r * ROWPAD + c * 4) * 4u;
            asm volatile("cp.async.cg.shared.global [%0], [%1], 16;"
                         :: "r"(d), "l"(src + (size_t)idx * 16) : "memory");
        }
    }
}

// Fused per-stage pass (512 threads, 8 threads/row):
//  1. i_sq from RAW fp32 (3-shfl reduce)
//  2. tf32 convert + k-pair permute in place: 8-block [x0..x7] -> [(x0,x4),(x1,x5),(x2,x6),(x3,x7)]
//     so the MMA B fragment (k, k+4) is one LDS.64.
static __device__ __forceinline__ void pass_tile(float* __restrict__ st,
                                                 float* __restrict__ isq, int tid) {
    int r = tid >> 3, q = tid & 7;
    float* row = st + r * ROWPAD + q * 8;
    float4 a = *reinterpret_cast<const float4*>(row);
    float4 b = *reinterpret_cast<const float4*>(row + 4);
    float s = fmaf(a.x, a.x, fmaf(a.y, a.y, fmaf(a.z, a.z, a.w * a.w)));
    s = fmaf(b.x, b.x, fmaf(b.y, b.y, fmaf(b.z, b.z, fmaf(b.w, b.w, s))));
    s += __shfl_xor_sync(0xffffffffu, s, 4);
    s += __shfl_xor_sync(0xffffffffu, s, 2);
    s += __shfl_xor_sync(0xffffffffu, s, 1);
    if (q == 0) isq[r] = s;
    uint2* w = reinterpret_cast<uint2*>(row);
    w[0] = make_uint2(f2tf32(a.x), f2tf32(b.x));
    w[1] = make_uint2(f2tf32(a.y), f2tf32(b.y));
    w[2] = make_uint2(f2tf32(a.z), f2tf32(b.z));
    w[3] = make_uint2(f2tf32(a.w), f2tf32(b.w));
}

__global__ void __launch_bounds__(512, 1)
cml_main(const float* __restrict__ items, float* __restrict__ out) {
    __shared__ float sm_it[2][TILE_N * ROWPAD];   // 2 x 17408 B
    __shared__ float sm_isq[2][TILE_N];

    int tid = threadIdx.x, wid = tid >> 5, lane = tid & 31;
    int grp = lane >> 2, tig = lane & 3;
    int uw = wid & 7;                              // user block: users [uw*32, uw*32+32)
    int nh = wid >> 3;                             // item half:  items [nh*32, nh*32+32)
    int bx = blockIdx.x, G = gridDim.x;
    int cnt = (NTILES - bx + G - 1) / G;

    uint32_t s0 = smem_u32(sm_it[0]), s1 = smem_u32(sm_it[1]);

    cp_tile(items, s0, bx * TILE_N, tid);
    CP_COMMIT();
    cp_tile(items, s1, (bx + G) * TILE_N, tid);
    CP_COMMIT();

    // A fragments (32 users per warp = 2 x m16, tf32), resident for the whole kernel.
    int r0a = uw * 32 + grp;                       // mf=0 base row; mf=1 adds 16
    uint32_t A[2][8][4];
    float nu[2][2];
#pragma unroll
    for (int mf = 0; mf < 2; mf++) {
        int rr = r0a + mf * 16;
#pragma unroll
        for (int ks = 0; ks < 8; ks++) {
            int c = ks * 8 + tig;
            A[mf][ks][0] = f2tf32(g_users[rr * DIM + c]);
            A[mf][ks][1] = f2tf32(g_users[(rr + 8) * DIM + c]);
            A[mf][ks][2] = f2tf32(g_users[rr * DIM + c + 4]);
            A[mf][ks][3] = f2tf32(g_users[(rr + 8) * DIM + c + 4]);
        }
        nu[mf][0] = -g_usq[rr];
        nu[mf][1] = -g_usq[rr + 8];
    }

    CP_WAIT1();
    __syncthreads();
    pass_tile(sm_it[0], sm_isq[0], tid);

    int nrow0 = nh * 32 + grp;                     // B fragment base row within tile
    int colb = nh * 32 + 2 * tig;                  // epilogue column base within tile

    for (int i = 0; i < cnt; i++) {
        int cur = i & 1, nxt = cur ^ 1;
        int tile_base = (bx + i * G) * TILE_N;
        __syncthreads();                           // pass(cur) results visible

        // ---- MMA: 32 users x 32 items, B = LDS.64 (permuted pairs), zero cvt ----
        float C[2][4][4];
#pragma unroll
        for (int mf = 0; mf < 2; mf++)
#pragma unroll
            for (int ni = 0; ni < 4; ni++)
#pragma unroll
                for (int q = 0; q < 4; q++) C[mf][ni][q] = 0.f;

        const uint2* bb = reinterpret_cast<const uint2*>(sm_it[cur]);
#pragma unroll
        for (int ks = 0; ks < 8; ks++) {
#pragma unroll
            for (int ni = 0; ni < 4; ni++) {
                uint2 b = bb[(nrow0 + ni * 8) * (ROWPAD / 2) + ks * 4 + tig];
                mma_tf32(C[0][ni], A[0][ks], b.x, b.y);
                mma_tf32(C[1][ni], A[1][ks], b.x, b.y);
            }
        }

        // Overlap: prefetch tile i+2 into stage cur while epilogue stores run.
        if (i + 1 < cnt) {
            __syncthreads();                       // all warps done reading sm_it[cur]
            cp_tile(items, cur ? s1 : s0, (bx + (i + 2) * G) * TILE_N, tid);
            CP_COMMIT();
        }

        // ---- epilogue: score = 2*cross - usq - isq, direct streaming stores ----
        const float* isq = sm_isq[cur];
        float2 iqv[4];
#pragma unroll
        for (int ni = 0; ni < 4; ni++)
            iqv[ni] = *reinterpret_cast<const float2*>(isq + colb + ni * 8);
#pragma unroll
        for (int mf = 0; mf < 2; mf++) {
            int rr = r0a + mf * 16;
            float* row0 = out + (size_t)rr * N_ITEMS_TOT;
            float* row1 = out + (size_t)(rr + 8) * N_ITEMS_TOT;
#pragma unroll
            for (int ni = 0; ni < 4; ni++) {
                int col = tile_base + colb + ni * 8;
                if (col < N_ITEMS_TOT) {
                    float n0x = nu[mf][0] - iqv[ni].x, n0y = nu[mf][0] - iqv[ni].y;
                    float n1x = nu[mf][1] - iqv[ni].x, n1y = nu[mf][1] - iqv[ni].y;
                    float2 v0, v1;
                    v0.x = fmaf(2.f, C[mf][ni][0], n0x);
                    v0.y = fmaf(2.f, C[mf][ni][1], n0y);
                    v1.x = fmaf(2.f, C[mf][ni][2], n1x);
                    v1.y = fmaf(2.f, C[mf][ni][3], n1y);
                    __stcs(reinterpret_cast<float2*>(row0 + col), v0);
                    __stcs(reinterpret_cast<float2*>(row1 + col), v1);
                }
            }
        }

        if (i + 1 < cnt) {
            CP_WAIT1();                            // tile i+1 landed
            __syncthreads();
            pass_tile(sm_it[nxt], sm_isq[nxt], tid);
        }
    }
}

extern "C" void kernel_launch(void* const* d_in, const int* in_sizes, int n_in,
                              void* d_out, int out_size) {
    (void)in_sizes; (void)n_in; (void)out_size;
    const int*   ids   = (const int*)d_in[0];
    const float* users = (const float*)d_in[1];
    const float* items = (const float*)d_in[2];
    float*       out   = (float*)d_out;

    int sms = 148;
    cudaDeviceGetAttribute(&sms, cudaDevAttrMultiProcessorCount, 0);
    int grid = sms < NTILES ? sms : NTILES;

    cml_prep_users<<<1, 256>>>(ids, users);
    cml_main<<<grid, 512>>>(items, out);
}

// round 12
// speedup vs baseline: 1.6631x; 1.6243x over previous
#include <cuda_runtime.h>
#include <cstdint>
#include <cstddef>

#define NSCORE       256
#define DIM          64
#define N_ITEMS_TOT  500000
#define TILE_N       64
#define NTILES       ((N_ITEMS_TOT + TILE_N - 1) / TILE_N)   // 7813
#define ROWPAD       68                                       // item tile row stride (floats)
#define STRIDE       68                                       // score stage row stride (floats)
                                                              // 68*4=272 B: 16B-aligned rows,
                                                              // +4-bank rotation per row

// dynamic smem layout (floats):
//  [0, 2*64*68)                two item tile stages
//  [IOFF_ISQ, +2*64)           i_sq per stage
//  [IOFF_STG, +256*68)         score staging buffer
#define IOFF_ISQ   (2 * TILE_N * ROWPAD)
#define IOFF_STG   (IOFF_ISQ + 2 * TILE_N)
#define SMEM_FLTS  (IOFF_STG + NSCORE * STRIDE)
#define SMEM_BYTES (SMEM_FLTS * 4)                            // 104960

// ---------------- baseline-PTX helpers (sm_80+, OK on .target sm_103) ----------------
static __device__ __forceinline__ uint32_t f2tf32(float x) {
    uint32_t r;
    asm("cvt.rna.tf32.f32 %0, %1;" : "=r"(r) : "f"(x));
    return r;
}
static __device__ __forceinline__ void mma_tf32(float d[4], const uint32_t a[4],
                                                const uint32_t b0, const uint32_t b1) {
    asm volatile("mma.sync.aligned.m16n8k8.row.col.f32.tf32.tf32.f32 "
                 "{%0,%1,%2,%3}, {%4,%5,%6,%7}, {%8,%9}, {%0,%1,%2,%3};"
                 : "+f"(d[0]), "+f"(d[1]), "+f"(d[2]), "+f"(d[3])
                 : "r"(a[0]), "r"(a[1]), "r"(a[2]), "r"(a[3]), "r"(b0), "r"(b1));
}
static __device__ __forceinline__ uint32_t smem_u32(const void* p) {
    uint32_t a;
    asm("{ .reg .u64 t; cvta.to.shared.u64 t, %1; cvt.u32.u64 %0, t; }" : "=r"(a) : "l"(p));
    return a;
}
#define CP_COMMIT()   asm volatile("cp.async.commit_group;" ::: "memory")
#define CP_WAIT1()    asm volatile("cp.async.wait_group 1;" ::: "memory")

// ---------------- persistent state: prologue -> main ----------------
__device__ __align__(16) float g_users[NSCORE * DIM];
__device__ float g_usq[NSCORE];

__global__ void cml_prep_users(const int* __restrict__ ids,
                               const float* __restrict__ U) {
    int m = threadIdx.x;                       // 256 threads, one user each
    const float* row = U + (size_t)ids[m] * DIM;
    float s = 0.f;
#pragma unroll 8
    for (int k = 0; k < DIM; k++) {
        float x = row[k];
        g_users[m * DIM + k] = x;
        s = fmaf(x, x, s);
    }
    g_usq[m] = s;
}

// cp.async one 64x64 fp32 item tile into a padded smem stage (raw fp32).
// OOB rows simply not loaded; store-sweep column guard contains garbage.
static __device__ __forceinline__ void cp_tile(const float* __restrict__ items,
                                               uint32_t dst_u32, long tile_base, int tid) {
    const char* src = reinterpret_cast<const char*>(items + (size_t)tile_base * DIM);
#pragma unroll
    for (int j = 0; j < 2; j++) {
        int idx = j * 512 + tid;               // 16B-chunk index (1024 per tile)
        int r = idx >> 4;                      // 16 chunks per item row
        int c = idx & 15;
        if (tile_base + r < N_ITEMS_TOT) {
            uint32_t d = dst_u32 + (uint32_t)(r * ROWPAD + c * 4) * 4u;
            asm volatile("cp.async.cg.shared.global [%0], [%1], 16;"
                         :: "r"(d), "l"(src + (size_t)idx * 16) : "memory");
        }
    }
}

// Fused per-stage pass: i_sq from raw fp32 + tf32 convert + k-pair permute
// in place ([x0..x7] -> [(x0,x4),(x1,x5),(x2,x6),(x3,x7)]) so B frag = 1 LDS.64.
static __device__ __forceinline__ void pass_tile(float* __restrict__ st,
                                                 float* __restrict__ isq, int tid) {
    int r = tid >> 3, q = tid & 7;
    float* row = st + r * ROWPAD + q * 8;
    float4 a = *reinterpret_cast<const float4*>(row);
    float4 b = *reinterpret_cast<const float4*>(row + 4);
    float s = fmaf(a.x, a.x, fmaf(a.y, a.y, fmaf(a.z, a.z, a.w * a.w)));
    s = fmaf(b.x, b.x, fmaf(b.y, b.y, fmaf(b.z, b.z, fmaf(b.w, b.w, s))));
    s += __shfl_xor_sync(0xffffffffu, s, 4);
    s += __shfl_xor_sync(0xffffffffu, s, 2);
    s += __shfl_xor_sync(0xffffffffu, s, 1);
    if (q == 0) isq[r] = s;
    uint2* w = reinterpret_cast<uint2*>(row);
    w[0] = make_uint2(f2tf32(a.x), f2tf32(b.x));
    w[1] = make_uint2(f2tf32(a.y), f2tf32(b.y));
    w[2] = make_uint2(f2tf32(a.z), f2tf32(b.z));
    w[3] = make_uint2(f2tf32(a.w), f2tf32(b.w));
}

__global__ void __launch_bounds__(512, 1)
cml_main(const float* __restrict__ items, float* __restrict__ out) {
    extern __shared__ float sm[];
    float* sm_it[2] = { sm, sm + TILE_N * ROWPAD };
    float* sm_isq   = sm + IOFF_ISQ;
    float* sm_stage = sm + IOFF_STG;

    int tid = threadIdx.x, wid = tid >> 5, lane = tid & 31;
    int grp = lane >> 2, tig = lane & 3;
    int uw = wid & 7;                              // user block: users [uw*32, uw*32+32)
    int nh = wid >> 3;                             // item half:  items [nh*32, nh*32+32)

    // Contiguous per-CTA tile chunk (sequential writes per out-row over time).
    int G = gridDim.x, b = blockIdx.x;
    long t0 = ((long)b * NTILES) / G;
    long t1 = ((long)(b + 1) * NTILES) / G;
    int cnt = (int)(t1 - t0);
    if (cnt == 0) return;

    uint32_t s0 = smem_u32(sm_it[0]), s1 = smem_u32(sm_it[1]);

    cp_tile(items, s0, t0 * TILE_N, tid);
    CP_COMMIT();
    cp_tile(items, s1, (t0 + 1) * TILE_N, tid);    // row guard no-ops past NTILES
    CP_COMMIT();

    // A fragments (32 users per warp = 2 x m16, tf32), resident for the kernel.
    int r0a = uw * 32 + grp;
    uint32_t A[2][8][4];
    float nu[2][2];
#pragma unroll
    for (int mf = 0; mf < 2; mf++) {
        int rr = r0a + mf * 16;
#pragma unroll
        for (int ks = 0; ks < 8; ks++) {
            int c = ks * 8 + tig;
            A[mf][ks][0] = f2tf32(g_users[rr * DIM + c]);
            A[mf][ks][1] = f2tf32(g_users[(rr + 8) * DIM + c]);
            A[mf][ks][2] = f2tf32(g_users[rr * DIM + c + 4]);
            A[mf][ks][3] = f2tf32(g_users[(rr + 8) * DIM + c + 4]);
        }
        nu[mf][0] = -g_usq[rr];
        nu[mf][1] = -g_usq[rr + 8];
    }

    CP_WAIT1();                                    // tile t0 landed
    __syncthreads();
    pass_tile(sm_it[0], sm_isq, tid);

    int nrow0 = nh * 32 + grp;                     // B fragment base row within tile
    int colb  = nh * 32 + 2 * tig;                 // score column base within tile
    int swrow = wid * 16 + (lane >> 4);            // sweep: base row parity part
    int swc   = (lane & 15) * 4;                   // sweep: column (floats)

    for (int i = 0; i < cnt; i++) {
        int cur = i & 1, nxt = cur ^ 1;
        long tile_base = (t0 + i) * TILE_N;
        __syncthreads();                           // pass(cur) done; stage free

        // ---- MMA: 32 users x 32 items, B = LDS.64 (permuted pairs) ----
        float C[2][4][4];
#pragma unroll
        for (int mf = 0; mf < 2; mf++)
#pragma unroll
            for (int ni = 0; ni < 4; ni++)
#pragma unroll
                for (int q = 0; q < 4; q++) C[mf][ni][q] = 0.f;

        const uint2* bb = reinterpret_cast<const uint2*>(sm_it[cur]);
#pragma unroll
        for (int ks = 0; ks < 8; ks++) {
#pragma unroll
            for (int ni = 0; ni < 4; ni++) {
                uint2 bv = bb[(nrow0 + ni * 8) * (ROWPAD / 2) + ks * 4 + tig];
                mma_tf32(C[0][ni], A[0][ks], bv.x, bv.y);
                mma_tf32(C[1][ni], A[1][ks], bv.x, bv.y);
            }
        }

        // ---- finalize scores in-reg, stage to smem (STS.64) ----
        const float* isq = sm_isq + cur * TILE_N;
#pragma unroll
        for (int mf = 0; mf < 2; mf++) {
            int rr = r0a + mf * 16;
#pragma unroll
            for (int ni = 0; ni < 4; ni++) {
                int cc = colb + ni * 8;
                float2 iq = *reinterpret_cast<const float2*>(isq + cc);
                float2 v0, v1;
                v0.x = fmaf(2.f, C[mf][ni][0], nu[mf][0] - iq.x);
                v0.y = fmaf(2.f, C[mf][ni][1], nu[mf][0] - iq.y);
                v1.x = fmaf(2.f, C[mf][ni][2], nu[mf][1] - iq.x);
                v1.y = fmaf(2.f, C[mf][ni][3], nu[mf][1] - iq.y);
                *reinterpret_cast<float2*>(sm_stage + rr * STRIDE + cc) = v0;
                *reinterpret_cast<float2*>(sm_stage + (rr + 8) * STRIDE + cc) = v1;
            }
        }
        __syncthreads();                           // stage complete; sm_it[cur] free

        // Prefetch tile i+2 into the just-freed stage (row guard handles end).
        cp_tile(items, cur ? s1 : s0, (t0 + i + 2) * TILE_N, tid);
        CP_COMMIT();

        // ---- store sweep: each STG.128 = 4 complete 128B lines ----
        // lanes 0-15: 256B contiguous of row r; lanes 16-31: row r+1.
#pragma unroll
        for (int k = 0; k < 8; k++) {
            int row = swrow + 2 * k;
            float4 v = *reinterpret_cast<const float4*>(sm_stage + row * STRIDE + swc);
            long col = tile_base + swc;
            if (col < N_ITEMS_TOT)                 // col,N both %4==0 -> all 4 valid
                __stcs(reinterpret_cast<float4*>(out + (size_t)row * N_ITEMS_TOT + col), v);
        }

        CP_WAIT1();                                // tile i+1 landed
        __syncthreads();                           // visible to all; sweep done
        if (i + 1 < cnt) pass_tile(sm_it[nxt], sm_isq + nxt * TILE_N, tid);
    }
}

extern "C" void kernel_launch(void* const* d_in, const int* in_sizes, int n_in,
                              void* d_out, int out_size) {
    (void)in_sizes; (void)n_in; (void)out_size;
    const int*   ids   = (const int*)d_in[0];
    const float* users = (const float*)d_in[1];
    const float* items = (const float*)d_in[2];
    float*       out   = (float*)d_out;

    cudaFuncSetAttribute(cml_main, cudaFuncAttributeMaxDynamicSharedMemorySize,
                         SMEM_BYTES);

    int sms = 148;
    cudaDeviceGetAttribute(&sms, cudaDevAttrMultiProcessorCount, 0);
    int grid = sms < NTILES ? sms : NTILES;

    cml_prep_users<<<1, 256>>>(ids, users);
    cml_main<<<grid, 512, SMEM_BYTES>>>(items, out);
}

// round 15
// speedup vs baseline: 1.9950x; 1.1996x over previous
#include <cuda_runtime.h>
#include <cstdint>
#include <cstddef>

#define NSCORE       256
#define DIM          64
#define N_ITEMS_TOT  500000
#define TILE_N       32
#define NTILES       (N_ITEMS_TOT / TILE_N)     // 15625, exact (500000 % 32 == 0)
#define ROWPAD       68                          // item row stride (floats): 64 + 4
#define STRIDE       36                          // stage row stride: 144B, 16B-aligned

// dynamic smem layout (floats):
//  [0, 2*32*68)              two item tile stages
//  [IOFF_ISQ, +2*32)         i_sq per stage
//  [IOFF_STG, +256*36)       score staging buffer
#define IOFF_ISQ   (2 * TILE_N * ROWPAD)
#define IOFF_STG   (IOFF_ISQ + 2 * TILE_N)
#define SMEM_FLTS  (IOFF_STG + NSCORE * STRIDE)
#define SMEM_BYTES (SMEM_FLTS * 4)               // 54784 -> 2 CTAs/SM

// ---------------- baseline-PTX helpers (sm_80+, OK on .target sm_103) ----------------
static __device__ __forceinline__ uint32_t f2tf32(float x) {
    uint32_t r;
    asm("cvt.rna.tf32.f32 %0, %1;" : "=r"(r) : "f"(x));
    return r;
}
static __device__ __forceinline__ void mma_tf32(float d[4], const uint32_t a[4],
                                                const uint32_t b0, const uint32_t b1) {
    asm volatile("mma.sync.aligned.m16n8k8.row.col.f32.tf32.tf32.f32 "
                 "{%0,%1,%2,%3}, {%4,%5,%6,%7}, {%8,%9}, {%0,%1,%2,%3};"
                 : "+f"(d[0]), "+f"(d[1]), "+f"(d[2]), "+f"(d[3])
                 : "r"(a[0]), "r"(a[1]), "r"(a[2]), "r"(a[3]), "r"(b0), "r"(b1));
}
static __device__ __forceinline__ uint32_t smem_u32(const void* p) {
    uint32_t a;
    asm("{ .reg .u64 t; cvta.to.shared.u64 t, %1; cvt.u32.u64 %0, t; }" : "=r"(a) : "l"(p));
    return a;
}
#define CP_COMMIT()   asm volatile("cp.async.commit_group;" ::: "memory")
#define CP_WAIT1()    asm volatile("cp.async.wait_group 1;" ::: "memory")

// ---------------- persistent state: prologue -> main ----------------
__device__ __align__(16) float g_users[NSCORE * DIM];
__device__ float g_usq[NSCORE];

__global__ void cml_prep_users(const int* __restrict__ ids,
                               const float* __restrict__ U) {
    int m = threadIdx.x;                       // 256 threads, one user each
    const float* row = U + (size_t)ids[m] * DIM;
    float s = 0.f;
#pragma unroll 8
    for (int k = 0; k < DIM; k++) {
        float x = row[k];
        g_users[m * DIM + k] = x;
        s = fmaf(x, x, s);
    }
    g_usq[m] = s;
}

// cp.async one 32x64 fp32 item tile into a padded smem stage (raw fp32).
// Whole-tile guard handles prefetch overrun past NTILES.
static __device__ __forceinline__ void cp_tile(const float* __restrict__ items,
                                               uint32_t dst_u32, long tile_base, int tid) {
    if (tile_base >= N_ITEMS_TOT) return;
    const char* src = reinterpret_cast<const char*>(items + (size_t)tile_base * DIM);
#pragma unroll
    for (int j = 0; j < 2; j++) {
        int idx = j * 256 + tid;               // 16B-chunk index (512 per tile)
        int r = idx >> 4;                      // 16 chunks per item row
        int c = idx & 15;
        uint32_t d = dst_u32 + (uint32_t)(r * ROWPAD + c * 4) * 4u;
        asm volatile("cp.async.cg.shared.global [%0], [%1], 16;"
                     :: "r"(d), "l"(src + (size_t)idx * 16) : "memory");
    }
}

// Fused per-stage pass (256 threads, 8 threads/row, 32 rows):
// i_sq from raw fp32 + tf32 convert + k-pair permute in place
// ([x0..x7] -> [(x0,x4),(x1,x5),(x2,x6),(x3,x7)]) so B frag = 1 LDS.64.
static __device__ __forceinline__ void pass_tile(float* __restrict__ st,
                                                 float* __restrict__ isq, int tid) {
    int r = tid >> 3, q = tid & 7;
    float* row = st + r * ROWPAD + q * 8;
    float4 a = *reinterpret_cast<const float4*>(row);
    float4 b = *reinterpret_cast<const float4*>(row + 4);
    float s = fmaf(a.x, a.x, fmaf(a.y, a.y, fmaf(a.z, a.z, a.w * a.w)));
    s = fmaf(b.x, b.x, fmaf(b.y, b.y, fmaf(b.z, b.z, fmaf(b.w, b.w, s))));
    s += __shfl_xor_sync(0xffffffffu, s, 4);
    s += __shfl_xor_sync(0xffffffffu, s, 2);
    s += __shfl_xor_sync(0xffffffffu, s, 1);
    if (q == 0) isq[r] = s;
    uint2* w = reinterpret_cast<uint2*>(row);
    w[0] = make_uint2(f2tf32(a.x), f2tf32(b.x));
    w[1] = make_uint2(f2tf32(a.y), f2tf32(b.y));
    w[2] = make_uint2(f2tf32(a.z), f2tf32(b.z));
    w[3] = make_uint2(f2tf32(a.w), f2tf32(b.w));
}

__global__ void __launch_bounds__(256, 2)
cml_main(const float* __restrict__ items, float* __restrict__ out) {
    extern __shared__ float sm[];
    float* sm_it[2] = { sm, sm + TILE_N * ROWPAD };
    float* sm_isq   = sm + IOFF_ISQ;
    float* sm_stage = sm + IOFF_STG;

    int tid = threadIdx.x, wid = tid >> 5, lane = tid & 31;
    int grp = lane >> 2, tig = lane & 3;       // B frag row/col-pair within quad
    // 8 warps: warp uw owns users [uw*32, uw*32+32), ALL 32 items of the tile.

    // Contiguous per-CTA tile chunk (sequential writes per out-row over time).
    int G = gridDim.x, b = blockIdx.x;
    long t0 = ((long)b * NTILES) / G;
    long t1 = ((long)(b + 1) * NTILES) / G;
    int cnt = (int)(t1 - t0);
    if (cnt == 0) return;

    uint32_t s0 = smem_u32(sm_it[0]), s1 = smem_u32(sm_it[1]);

    cp_tile(items, s0, t0 * TILE_N, tid);
    CP_COMMIT();
    cp_tile(items, s1, (t0 + 1) * TILE_N, tid);
    CP_COMMIT();

    // A fragments (32 users per warp = 2 x m16, tf32), resident for the kernel.
    int r0a = wid * 32 + grp;
    uint32_t A[2][8][4];
    float nu[2][2];
#pragma unroll
    for (int mf = 0; mf < 2; mf++) {
        int rr = r0a + mf * 16;
#pragma unroll
        for (int ks = 0; ks < 8; ks++) {
            int c = ks * 8 + tig;
            A[mf][ks][0] = f2tf32(g_users[rr * DIM + c]);
            A[mf][ks][1] = f2tf32(g_users[(rr + 8) * DIM + c]);
            A[mf][ks][2] = f2tf32(g_users[rr * DIM + c + 4]);
            A[mf][ks][3] = f2tf32(g_users[(rr + 8) * DIM + c + 4]);
        }
        nu[mf][0] = -g_usq[rr];
        nu[mf][1] = -g_usq[rr + 8];
    }

    CP_WAIT1();                                // tile t0 landed
    __syncthreads();
    pass_tile(sm_it[0], sm_isq, tid);

    int colb = 2 * tig;                        // score column base within tile
    int swc  = (lane & 7) * 4;                 // sweep column (floats)
    int swr  = lane >> 3;                      // sweep row-within-4

    for (int i = 0; i < cnt; i++) {
        int cur = i & 1, nxt = cur ^ 1;
        long tile_base = (t0 + i) * TILE_N;
        __syncthreads();                       // pass(cur) done; stage free

        // ---- MMA: 32 users x 32 items, B = LDS.64 (permuted pairs) ----
        float C[2][4][4];
#pragma unroll
        for (int mf = 0; mf < 2; mf++)
#pragma unroll
            for (int ni = 0; ni < 4; ni++)
#pragma unroll
                for (int q = 0; q < 4; q++) C[mf][ni][q] = 0.f;

        const uint2* bb = reinterpret_cast<const uint2*>(sm_it[cur]);
#pragma unroll
        for (int ks = 0; ks < 8; ks++) {
#pragma unroll
            for (int ni = 0; ni < 4; ni++) {
                uint2 bv = bb[(grp + ni * 8) * (ROWPAD / 2) + ks * 4 + tig];
                mma_tf32(C[0][ni], A[0][ks], bv.x, bv.y);
                mma_tf32(C[1][ni], A[1][ks], bv.x, bv.y);
            }
        }

        // ---- finalize scores in-reg, stage to smem (STS.64) ----
        const float* isq = sm_isq + cur * TILE_N;
#pragma unroll
        for (int mf = 0; mf < 2; mf++) {
            int rr = r0a + mf * 16;
#pragma unroll
            for (int ni = 0; ni < 4; ni++) {
                int cc = colb + ni * 8;
                float2 iq = *reinterpret_cast<const float2*>(isq + cc);
                float2 v0, v1;
                v0.x = fmaf(2.f, C[mf][ni][0], nu[mf][0] - iq.x);
                v0.y = fmaf(2.f, C[mf][ni][1], nu[mf][0] - iq.y);
                v1.x = fmaf(2.f, C[mf][ni][2], nu[mf][1] - iq.x);
                v1.y = fmaf(2.f, C[mf][ni][3], nu[mf][1] - iq.y);
                *reinterpret_cast<float2*>(sm_stage + rr * STRIDE + cc) = v0;
                *reinterpret_cast<float2*>(sm_stage + (rr + 8) * STRIDE + cc) = v1;
            }
        }
        __syncthreads();                       // stage complete; sm_it[cur] free

        // Prefetch tile i+2 into the just-freed stage (whole-tile guard at end).
        cp_tile(items, cur ? s1 : s0, (t0 + i + 2) * TILE_N, tid);
        CP_COMMIT();

        // ---- store sweep: each STG.128 = 4 complete 128B lines (4 rows) ----
        // Warp w covers rows [w*32, w*32+32): 8 iterations x 4 rows.
        // Tile is always full (500000 % 32 == 0) -> no column guard.
#pragma unroll
        for (int k = 0; k < 8; k++) {
            int row = wid * 32 + k * 4 + swr;
            float4 v = *reinterpret_cast<const float4*>(sm_stage + row * STRIDE + swc);
            __stcs(reinterpret_cast<float4*>(out + (size_t)row * N_ITEMS_TOT
                                             + tile_base + swc), v);
        }

        CP_WAIT1();                            // tile i+1 landed
        __syncthreads();                       // sweep done; cp visible
        if (i + 1 < cnt) pass_tile(sm_it[nxt], sm_isq + nxt * TILE_N, tid);
    }
}

extern "C" void kernel_launch(void* const* d_in, const int* in_sizes, int n_in,
                              void* d_out, int out_size) {
    (void)in_sizes; (void)n_in; (void)out_size;
    const int*   ids   = (const int*)d_in[0];
    const float* users = (const float*)d_in[1];
    const float* items = (const float*)d_in[2];
    float*       out   = (float*)d_out;

    cudaFuncSetAttribute(cml_main, cudaFuncAttributeMaxDynamicSharedMemorySize,
                         SMEM_BYTES);

    int sms = 148;
    cudaDeviceGetAttribute(&sms, cudaDevAttrMultiProcessorCount, 0);
    int grid = 2 * sms;                        // 2 co-resident CTAs per SM
    if (grid > NTILES) grid = NTILES;

    cml_prep_users<<<1, 256>>>(ids, users);
    cml_main<<<grid, 256, SMEM_BYTES>>>(items, out);
}

// round 16
// speedup vs baseline: 2.1390x; 1.0722x over previous
#include <cuda_runtime.h>
#include <cstdint>
#include <cstddef>

#define NSCORE       256
#define DIM          64
#define N_ITEMS_TOT  500000
#define TILE_N       32
#define NTILES       (N_ITEMS_TOT / TILE_N)     // 15625, exact (500000 % 32 == 0)
#define ROWPAD       72                          // item row stride: 36 u2 ≡ 4 (mod 16)
                                                 //  -> conflict-free LDS.64 B fragments
#define STRIDE       40                          // stage row stride: 20 u2 ≡ 4 (mod 16)
                                                 //  -> conflict-free STS.64; 160B rows, 16B-aligned

// dynamic smem layout (floats):
//  [0, 2*32*72)              two item tile stages
//  [IOFF_ISQ, +2*32)         i_sq per stage
//  [IOFF_STG, +256*40)       score staging buffer
#define IOFF_ISQ   (2 * TILE_N * ROWPAD)
#define IOFF_STG   (IOFF_ISQ + 2 * TILE_N)
#define SMEM_FLTS  (IOFF_STG + NSCORE * STRIDE)
#define SMEM_BYTES (SMEM_FLTS * 4)               // 59648 -> 2 CTAs/SM

// ---------------- baseline-PTX helpers (sm_80+, OK on .target sm_103) ----------------
static __device__ __forceinline__ uint32_t f2tf32(float x) {
    uint32_t r;
    asm("cvt.rna.tf32.f32 %0, %1;" : "=r"(r) : "f"(x));
    return r;
}
static __device__ __forceinline__ void mma_tf32(float d[4], const uint32_t a[4],
                                                const uint32_t b0, const uint32_t b1) {
    asm volatile("mma.sync.aligned.m16n8k8.row.col.f32.tf32.tf32.f32 "
                 "{%0,%1,%2,%3}, {%4,%5,%6,%7}, {%8,%9}, {%0,%1,%2,%3};"
                 : "+f"(d[0]), "+f"(d[1]), "+f"(d[2]), "+f"(d[3])
                 : "r"(a[0]), "r"(a[1]), "r"(a[2]), "r"(a[3]), "r"(b0), "r"(b1));
}
static __device__ __forceinline__ uint32_t smem_u32(const void* p) {
    uint32_t a;
    asm("{ .reg .u64 t; cvta.to.shared.u64 t, %1; cvt.u32.u64 %0, t; }" : "=r"(a) : "l"(p));
    return a;
}
#define CP_COMMIT()   asm volatile("cp.async.commit_group;" ::: "memory")
#define CP_WAIT1()    asm volatile("cp.async.wait_group 1;" ::: "memory")

// ---------------- persistent state: prologue -> main ----------------
__device__ __align__(16) float g_users[NSCORE * DIM];
__device__ float g_usq[NSCORE];

__global__ void cml_prep_users(const int* __restrict__ ids,
                               const float* __restrict__ U) {
    int m = threadIdx.x;                       // 256 threads, one user each
    const float* row = U + (size_t)ids[m] * DIM;
    float s = 0.f;
#pragma unroll 8
    for (int k = 0; k < DIM; k++) {
        float x = row[k];
        g_users[m * DIM + k] = x;
        s = fmaf(x, x, s);
    }
    g_usq[m] = s;
}

// cp.async one 32x64 fp32 item tile into a padded smem stage (raw fp32).
// Whole-tile guard handles prefetch overrun past NTILES.
static __device__ __forceinline__ void cp_tile(const float* __restrict__ items,
                                               uint32_t dst_u32, long tile_base, int tid) {
    if (tile_base >= N_ITEMS_TOT) return;
    const char* src = reinterpret_cast<const char*>(items + (size_t)tile_base * DIM);
#pragma unroll
    for (int j = 0; j < 2; j++) {
        int idx = j * 256 + tid;               // 16B-chunk index (512 per tile)
        int r = idx >> 4;                      // 16 chunks per item row
        int c = idx & 15;
        uint32_t d = dst_u32 + (uint32_t)(r * ROWPAD + c * 4) * 4u;
        asm volatile("cp.async.cg.shared.global [%0], [%1], 16;"
                     :: "r"(d), "l"(src + (size_t)idx * 16) : "memory");
    }
}

// Fused per-stage pass (256 threads, 8 threads/row, 32 rows):
// i_sq from raw fp32 + tf32 convert + k-pair permute in place
// ([x0..x7] -> [(x0,x4),(x1,x5),(x2,x6),(x3,x7)]) so B frag = 1 LDS.64.
static __device__ __forceinline__ void pass_tile(float* __restrict__ st,
                                                 float* __restrict__ isq, int tid) {
    int r = tid >> 3, q = tid & 7;
    float* row = st + r * ROWPAD + q * 8;
    float4 a = *reinterpret_cast<const float4*>(row);
    float4 b = *reinterpret_cast<const float4*>(row + 4);
    float s = fmaf(a.x, a.x, fmaf(a.y, a.y, fmaf(a.z, a.z, a.w * a.w)));
    s = fmaf(b.x, b.x, fmaf(b.y, b.y, fmaf(b.z, b.z, fmaf(b.w, b.w, s))));
    s += __shfl_xor_sync(0xffffffffu, s, 4);
    s += __shfl_xor_sync(0xffffffffu, s, 2);
    s += __shfl_xor_sync(0xffffffffu, s, 1);
    if (q == 0) isq[r] = s;
    uint2* w = reinterpret_cast<uint2*>(row);
    w[0] = make_uint2(f2tf32(a.x), f2tf32(b.x));
    w[1] = make_uint2(f2tf32(a.y), f2tf32(b.y));
    w[2] = make_uint2(f2tf32(a.z), f2tf32(b.z));
    w[3] = make_uint2(f2tf32(a.w), f2tf32(b.w));
}

__global__ void __launch_bounds__(256, 2)
cml_main(const float* __restrict__ items, float* __restrict__ out) {
    extern __shared__ float sm[];
    float* sm_it[2] = { sm, sm + TILE_N * ROWPAD };
    float* sm_isq   = sm + IOFF_ISQ;
    float* sm_stage = sm + IOFF_STG;

    int tid = threadIdx.x, wid = tid >> 5, lane = tid & 31;
    int grp = lane >> 2, tig = lane & 3;       // B frag row/col-pair within quad
    // 8 warps: warp uw owns users [uw*32, uw*32+32), ALL 32 items of the tile.

    // Contiguous per-CTA tile chunk (sequential writes per out-row over time).
    int G = gridDim.x, b = blockIdx.x;
    long t0 = ((long)b * NTILES) / G;
    long t1 = ((long)(b + 1) * NTILES) / G;
    int cnt = (int)(t1 - t0);
    if (cnt == 0) return;

    uint32_t s0 = smem_u32(sm_it[0]), s1 = smem_u32(sm_it[1]);

    cp_tile(items, s0, t0 * TILE_N, tid);
    CP_COMMIT();
    cp_tile(items, s1, (t0 + 1) * TILE_N, tid);
    CP_COMMIT();

    // A fragments (32 users per warp = 2 x m16, tf32), resident for the kernel.
    int r0a = wid * 32 + grp;
    uint32_t A[2][8][4];
    float nu[2][2];
#pragma unroll
    for (int mf = 0; mf < 2; mf++) {
        int rr = r0a + mf * 16;
#pragma unroll
        for (int ks = 0; ks < 8; ks++) {
            int c = ks * 8 + tig;
            A[mf][ks][0] = f2tf32(g_users[rr * DIM + c]);
            A[mf][ks][1] = f2tf32(g_users[(rr + 8) * DIM + c]);
            A[mf][ks][2] = f2tf32(g_users[rr * DIM + c + 4]);
            A[mf][ks][3] = f2tf32(g_users[(rr + 8) * DIM + c + 4]);
        }
        nu[mf][0] = -g_usq[rr];
        nu[mf][1] = -g_usq[rr + 8];
    }

    CP_WAIT1();                                // tile t0 landed
    __syncthreads();
    pass_tile(sm_it[0], sm_isq, tid);

    int colb = 2 * tig;                        // score column base within tile
    int swc  = (lane & 7) * 4;                 // sweep column (floats)
    int swr  = lane >> 3;                      // sweep row-within-4

    for (int i = 0; i < cnt; i++) {
        int cur = i & 1, nxt = cur ^ 1;
        long tile_base = (t0 + i) * TILE_N;
        __syncthreads();                       // pass(cur) done; stage free

        // ---- MMA: 32 users x 32 items, B = LDS.64 (permuted pairs) ----
        // Stride 36 u2 ≡ 4 (mod 16): each 16-lane half hits 4*grp+tig = all
        // 16 double-banks exactly once -> minimum 2 wavefronts per LDS.64.
        float C[2][4][4];
#pragma unroll
        for (int mf = 0; mf < 2; mf++)
#pragma unroll
            for (int ni = 0; ni < 4; ni++)
#pragma unroll
                for (int q = 0; q < 4; q++) C[mf][ni][q] = 0.f;

        const uint2* bb = reinterpret_cast<const uint2*>(sm_it[cur]);
#pragma unroll
        for (int ks = 0; ks < 8; ks++) {
#pragma unroll
            for (int ni = 0; ni < 4; ni++) {
                uint2 bv = bb[(grp + ni * 8) * (ROWPAD / 2) + ks * 4 + tig];
                mma_tf32(C[0][ni], A[0][ks], bv.x, bv.y);
                mma_tf32(C[1][ni], A[1][ks], bv.x, bv.y);
            }
        }

        // ---- finalize scores in-reg, stage to smem (STS.64, conflict-free) ----
        const float* isq = sm_isq + cur * TILE_N;
#pragma unroll
        for (int mf = 0; mf < 2; mf++) {
            int rr = r0a + mf * 16;
#pragma unroll
            for (int ni = 0; ni < 4; ni++) {
                int cc = colb + ni * 8;
                float2 iq = *reinterpret_cast<const float2*>(isq + cc);
                float2 v0, v1;
                v0.x = fmaf(2.f, C[mf][ni][0], nu[mf][0] - iq.x);
                v0.y = fmaf(2.f, C[mf][ni][1], nu[mf][0] - iq.y);
                v1.x = fmaf(2.f, C[mf][ni][2], nu[mf][1] - iq.x);
                v1.y = fmaf(2.f, C[mf][ni][3], nu[mf][1] - iq.y);
                *reinterpret_cast<float2*>(sm_stage + rr * STRIDE + cc) = v0;
                *reinterpret_cast<float2*>(sm_stage + (rr + 8) * STRIDE + cc) = v1;
            }
        }
        __syncthreads();                       // stage complete; sm_it[cur] free

        // Prefetch tile i+2 into the just-freed stage (whole-tile guard at end).
        cp_tile(items, cur ? s1 : s0, (t0 + i + 2) * TILE_N, tid);
        CP_COMMIT();

        // ---- store sweep: each STG.128 = 4 complete 128B lines (4 rows) ----
        // Warp w covers rows [w*32, w*32+32): 8 iterations x 4 rows.
        // Tile is always full (500000 % 32 == 0) -> no column guard.
#pragma unroll
        for (int k = 0; k < 8; k++) {
            int row = wid * 32 + k * 4 + swr;
            float4 v = *reinterpret_cast<const float4*>(sm_stage + row * STRIDE + swc);
            __stcs(reinterpret_cast<float4*>(out + (size_t)row * N_ITEMS_TOT
                                             + tile_base + swc), v);
        }

        CP_WAIT1();                            // tile i+1 landed
        __syncthreads();                       // sweep done; cp visible
        if (i + 1 < cnt) pass_tile(sm_it[nxt], sm_isq + nxt * TILE_N, tid);
    }
}

extern "C" void kernel_launch(void* const* d_in, const int* in_sizes, int n_in,
                              void* d_out, int out_size) {
    (void)in_sizes; (void)n_in; (void)out_size;
    const int*   ids   = (const int*)d_in[0];
    const float* users = (const float*)d_in[1];
    const float* items = (const float*)d_in[2];
    float*       out   = (float*)d_out;

    cudaFuncSetAttribute(cml_main, cudaFuncAttributeMaxDynamicSharedMemorySize,
                         SMEM_BYTES);

    int sms = 148;
    cudaDeviceGetAttribute(&sms, cudaDevAttrMultiProcessorCount, 0);
    int grid = 2 * sms;                        // 2 co-resident CTAs per SM
    if (grid > NTILES) grid = NTILES;

    cml_prep_users<<<1, 256>>>(ids, users);
    cml_main<<<grid, 256, SMEM_BYTES>>>(items, out);
}